// round 14
// baseline (speedup 1.0000x reference)
#include <cuda_runtime.h>
#include <cuda_fp16.h>
#include <cstdint>

#define T 256
#define H 128
#define V 60
#define M 8
#define NT 512          // 16 warps: (wj 0..7) x (wk 0..1) split-K
#define NCTA 128
#define PSW 132

// ---- shared layout (float words) -------------------------------------------
// main fp16 tile: 256 pairs (uint2) per buffer. pair idx = kt*32 + c*8 + (n^c)
//   bytes [0:4) = f16x2 k {kt*16+2c, +1}, [4:8) = f16x2 k {kt*16+8+2c, +1}, col n
// fp8 tiles: 128 pairs per buffer. pair idx = q*32 + c*8 + (n^c)
//   bytes [0:4) = e4m3 k {q*32+4c..+3}, [4:8) = e4m3 k {q*32+16+4c..+3}
#define MAIN_OFF(s) ((s) * 512)
#define FLO_OFF(s)  (1024 + (s) * 256)
#define FH_OFF(s)   (1536 + (s) * 256)
#define X_OFF       2048
#define PS_OFF      3072
#define LS_OFF      (PS_OFF + V * PSW)
#define TOK_OFF     (LS_OFF + M * H)
#define SMWORDS     (TOK_OFF + M * T)

__device__ __align__(16) float g_proj[V * H];

__device__ __forceinline__ float fast_tanh(float x) {
    float e = __expf(2.0f * x);
    return 1.0f - __fdividef(2.0f, e + 1.0f);
}
__device__ __forceinline__ void mma_f16(float* c, const uint32_t* a,
                                        uint32_t b0, uint32_t b1) {
    asm volatile(
        "mma.sync.aligned.m16n8k16.row.col.f32.f16.f16.f32 "
        "{%0,%1,%2,%3}, {%4,%5,%6,%7}, {%8,%9}, {%0,%1,%2,%3};"
        : "+f"(c[0]), "+f"(c[1]), "+f"(c[2]), "+f"(c[3])
        : "r"(a[0]), "r"(a[1]), "r"(a[2]), "r"(a[3]), "r"(b0), "r"(b1));
}
__device__ __forceinline__ void mma_fp8(float* c, const uint32_t* a,
                                        uint32_t b0, uint32_t b1) {
    asm volatile(
        "mma.sync.aligned.m16n8k32.row.col.f32.e4m3.e4m3.f32 "
        "{%0,%1,%2,%3}, {%4,%5,%6,%7}, {%8,%9}, {%0,%1,%2,%3};"
        : "+f"(c[0]), "+f"(c[1]), "+f"(c[2]), "+f"(c[3])
        : "r"(a[0]), "r"(a[1]), "r"(a[2]), "r"(a[3]), "r"(b0), "r"(b1));
}
__device__ __forceinline__ uint16_t e4m3x2(float x1, float x0) {  // low byte = x0
    uint16_t r;
    asm("cvt.rn.satfinite.e4m3x2.f32 %0, %1, %2;" : "=h"(r) : "f"(x1), "f"(x0));
    return r;
}
__device__ __forceinline__ uint32_t pack_e4m3_4(float x0, float x1, float x2, float x3) {
    uint16_t lo = e4m3x2(x1, x0);
    uint16_t hi = e4m3x2(x3, x2);
    return ((uint32_t)hi << 16) | lo;
}
__device__ __forceinline__ uint32_t pack_f16(float a, float b) {  // low = a
    __half2 h = __floats2half2_rn(a, b);
    return *(uint32_t*)&h;
}

// ---------------------------------------------------------------------------
// Stage 1: proj[v][j] = emb[v] . W_ih[j]
// ---------------------------------------------------------------------------
__global__ void proj_kernel(const float* __restrict__ emb,
                            const float* __restrict__ W_ih) {
    __shared__ float e[H];
    const int v = blockIdx.x;
    const int j = threadIdx.x;
    e[j] = emb[v * H + j];
    __syncthreads();
    const float* w = W_ih + j * H;
    float s = 0.f;
#pragma unroll 16
    for (int k = 0; k < H; ++k) s += e[k] * w[k];
    g_proj[v * H + j] = s;
}

// ---------------------------------------------------------------------------
// Stage 2: split-K persistent recurrence. Warp (wj, wk): j-tile wj (16 j),
// k in [64*wk, 64*wk+64). 4 fp16 + 4 fp8 MMAs/warp/step; partials combined
// via smem exchange; each thread finalizes 2 outputs (one j row, cols mA,mB).
// ---------------------------------------------------------------------------
__global__ __launch_bounds__(NT, 1)
void rnn_kernel(const int* __restrict__ x,
                const int* __restrict__ lengths,
                const float* __restrict__ W_hh,
                const float* __restrict__ W_fc,
                const float* __restrict__ b_fc,
                float* __restrict__ out) {
    extern __shared__ float sm[];
    float*  Ps  = sm + PS_OFF;
    float*  Ls  = sm + LS_OFF;
    int*    Tok = (int*)(sm + TOK_OFF);
    float2* X2  = (float2*)(sm + X_OFF);   // [0:256) from wk=1, [256:512) from wk=0

    const int tid = threadIdx.x;
    const int w = tid >> 5, l = tid & 31;
    const int wj = w & 7, wk = w >> 3;
    const int b0 = blockIdx.x * M;

    for (int idx = tid; idx < V * H; idx += NT) {
        int v = idx >> 7, j = idx & 127;
        Ps[v * PSW + j] = g_proj[idx];
    }
    for (int idx = tid; idx < M * T; idx += NT)
        Tok[idx] = x[b0 * T + idx];

    const int g = l >> 2, c = l & 3;
    const int j1 = wj * 16 + g;
    const int j2 = j1 + 8;
    const int jrow = wk ? j2 : j1;          // the j this thread finalizes
    const int mA = 2 * c, mB = 2 * c + 1;

    // --- A fragments (this warp's k-half only) ------------------------------
    uint32_t Af[4][4];
#pragma unroll
    for (int t = 0; t < 4; ++t) {
        const int kt = wk * 4 + t;
        const float* r1 = W_hh + j1 * H + kt * 16;
        const float* r2 = W_hh + j2 * H + kt * 16;
        Af[t][0] = pack_f16(r1[2 * c], r1[2 * c + 1]);
        Af[t][1] = pack_f16(r2[2 * c], r2[2 * c + 1]);
        Af[t][2] = pack_f16(r1[8 + 2 * c], r1[8 + 2 * c + 1]);
        Af[t][3] = pack_f16(r2[8 + 2 * c], r2[8 + 2 * c + 1]);
    }
    uint32_t AW8[2][4], AL8[2][4];
#pragma unroll
    for (int qq = 0; qq < 2; ++qq) {
        const int q = wk * 2 + qq;
        const int rows[2] = { j1, j2 };
#pragma unroll
        for (int half = 0; half < 2; ++half) {
#pragma unroll
            for (int rr = 0; rr < 2; ++rr) {
                const float* p = W_hh + rows[rr] * H + q * 32 + half * 16 + 4 * c;
                float w0 = p[0], w1 = p[1], w2 = p[2], w3 = p[3];
                int reg = half * 2 + rr;
                AW8[qq][reg] = pack_e4m3_4(w0, w1, w2, w3);
                float l0 = (w0 - __half2float(__float2half_rn(w0))) * 2048.f;
                float l1 = (w1 - __half2float(__float2half_rn(w1))) * 2048.f;
                float l2 = (w2 - __half2float(__float2half_rn(w2))) * 2048.f;
                float l3 = (w3 - __half2float(__float2half_rn(w3))) * 2048.f;
                AL8[qq][reg] = pack_e4m3_4(l0, l1, l2, l3);
            }
        }
    }

    const int lenA = lengths[b0 + mA];
    const int lenB = lengths[b0 + mB];

    // --- read offset (pair idx within kt/q block) ---
    const int rof = c * 8 + (g ^ c);

    // --- producer byte offsets for (jrow, mA/mB) ---
    const int ktp = jrow >> 4, r16 = jrow & 15;
    const int cp16 = (r16 & 7) >> 1;
    const int mtail = ((r16 >> 3) << 2) + ((r16 & 1) << 1);
    const int mbA = ((ktp * 32 + cp16 * 8 + (mA ^ cp16)) << 3) + mtail;
    const int mbB = ((ktp * 32 + cp16 * 8 + (mB ^ cp16)) << 3) + mtail;
    const int qp = jrow >> 5, r32 = jrow & 31;
    const int cp8 = (r32 & 15) >> 2;
    const int ftail = ((r32 >> 4) << 2) + (r32 & 3);
    const int f8A = ((qp * 32 + cp8 * 8 + (mA ^ cp8)) << 3) + ftail;
    const int f8B = ((qp * 32 + cp8 * 8 + (mB ^ cp8)) << 3) + ftail;

    __syncthreads();

    auto store_h = [&](int s, float hA, float hB) {
        char* mn = (char*)(sm + MAIN_OFF(s));
        __half fa = __float2half_rn(hA), fb = __float2half_rn(hB);
        *(unsigned short*)(mn + mbA) = __half_as_ushort(fa);
        *(unsigned short*)(mn + mbB) = __half_as_ushort(fb);
        float la = (hA - __half2float(fa)) * 4096.f;
        float lb = (hB - __half2float(fb)) * 4096.f;
        uint16_t pl = e4m3x2(lb, la);
        char* fl = (char*)(sm + FLO_OFF(s));
        fl[f8A] = (char)pl;
        fl[f8B] = (char)(pl >> 8);
        uint16_t ph = e4m3x2(hB, hA);
        char* fh = (char*)(sm + FH_OFF(s));
        fh[f8A] = (char)ph;
        fh[f8B] = (char)(ph >> 8);
    };

    // --- peel step 0: h1 = tanh(proj[x_0]) ---
    {
        int tkA = Tok[mA * T], tkB = Tok[mB * T];
        float hA = fast_tanh(Ps[tkA * PSW + jrow]);
        float hB = fast_tanh(Ps[tkB * PSW + jrow]);
        if (lenA == 1) Ls[mA * H + jrow] = hA;
        if (lenB == 1) Ls[mB * H + jrow] = hB;
        store_h(0, hA, hB);
    }
    __syncthreads();

    const float s1 = 1.f / 4096.f, s2 = 1.f / 2048.f;

    for (int i = 1; i < T; ++i) {
        const int rs = (i - 1) & 1, ws = i & 1;
        const uint2* Mc = (const uint2*)(sm + MAIN_OFF(rs));
        const uint2* Lc = (const uint2*)(sm + FLO_OFF(rs));
        const uint2* Hc = (const uint2*)(sm + FH_OFF(rs));

        int tkA = Tok[mA * T + i], tkB = Tok[mB * T + i];
        float pA = Ps[tkA * PSW + jrow];
        float pB = Ps[tkB * PSW + jrow];

        float aM0[4] = {0.f, 0.f, 0.f, 0.f}, aM1[4] = {0.f, 0.f, 0.f, 0.f};
        float aA[4]  = {0.f, 0.f, 0.f, 0.f}, aB[4]  = {0.f, 0.f, 0.f, 0.f};

#pragma unroll
        for (int t = 0; t < 4; ++t) {
            const int kt = wk * 4 + t;
            uint2 bb = Mc[kt * 32 + rof];
            mma_f16((t & 1) ? aM1 : aM0, Af[t], bb.x, bb.y);
        }
#pragma unroll
        for (int qq = 0; qq < 2; ++qq) {
            const int q = wk * 2 + qq;
            uint2 lo8 = Lc[q * 32 + rof];
            mma_fp8(aA, AW8[qq], lo8.x, lo8.y);
            uint2 hi8 = Hc[q * 32 + rof];
            mma_fp8(aB, AL8[qq], hi8.x, hi8.y);
        }

        // partials: p0=(j1,mA), p1=(j1,mB), p2=(j2,mA), p3=(j2,mB)
        float p0 = (aM0[0] + aM1[0]) + aA[0] * s1 + aB[0] * s2;
        float p1 = (aM0[1] + aM1[1]) + aA[1] * s1 + aB[1] * s2;
        float p2 = (aM0[2] + aM1[2]) + aA[2] * s1 + aB[2] * s2;
        float p3 = (aM0[3] + aM1[3]) + aA[3] * s1 + aB[3] * s2;

        if (wk == 0) X2[256 + wj * 32 + l] = make_float2(p2, p3);
        else         X2[wj * 32 + l]       = make_float2(p0, p1);
        __syncthreads();
        float2 o = wk ? X2[256 + wj * 32 + l] : X2[wj * 32 + l];

        float zA = (wk ? p2 : p0) + o.x + pA;
        float zB = (wk ? p3 : p1) + o.y + pB;
        float hA = fast_tanh(zA);
        float hB = fast_tanh(zB);

        if (i == lenA - 1) Ls[mA * H + jrow] = hA;
        if (i == lenB - 1) Ls[mB * H + jrow] = hB;
        store_h(ws, hA, hB);
        __syncthreads();
    }

    // --- FC epilogue: out[b] = Ls[b] @ W_fc^T + b_fc (reuse Ps for W_fc) ---
    for (int idx = tid; idx < V * H; idx += NT) {
        int v = idx >> 7, j = idx & 127;
        Ps[v * PSW + j] = W_fc[idx];
    }
    __syncthreads();

    for (int p = tid; p < M * V; p += NT) {
        const int m = p / V, v = p % V;
        const float* lr = Ls + m * H;
        const float* wr = Ps + v * PSW;
        float s = b_fc[v];
#pragma unroll 8
        for (int k = 0; k < H; ++k) s += lr[k] * wr[k];
        out[(b0 + m) * V + v] = s;
    }
}

extern "C" void kernel_launch(void* const* d_in, const int* in_sizes, int n_in,
                              void* d_out, int out_size) {
    const int*   x       = (const int*)d_in[0];
    const int*   lengths = (const int*)d_in[1];
    const float* emb     = (const float*)d_in[2];
    const float* W_ih    = (const float*)d_in[3];
    const float* W_hh    = (const float*)d_in[4];
    const float* W_fc    = (const float*)d_in[5];
    const float* b_fc    = (const float*)d_in[6];
    float*       out     = (float*)d_out;

    proj_kernel<<<V, H>>>(emb, W_ih);

    size_t smem = (size_t)SMWORDS * sizeof(float);
    cudaFuncSetAttribute(rnn_kernel, cudaFuncAttributeMaxDynamicSharedMemorySize,
                         (int)smem);
    rnn_kernel<<<NCTA, NT, smem>>>(x, lengths, W_hh, W_fc, b_fc, out);
}